// round 9
// baseline (speedup 1.0000x reference)
#include <cuda_runtime.h>

// MaskedMSE: B=16, C=4, H=W=512 — single kernel, hierarchical device-side tail.
// input : d_in[0]  float32 [16, 4, 512, 512]
// target: d_in[1]  float32 [16, 5, 512, 512]  (channel 4 is the {0,1} mask)
// out   : d_out    float32 [1]
//
// 16 batches x 64 blocks. Each block writes a (masked SSE, count) partial.
// Level 1: the last block of each BATCH (per-batch ticket) folds that batch's
//          64 partials -> per_b = cnt>0 ? sse/(C*cnt) : 0   (16 folds, parallel)
// Level 2: the last of the 16 folders (global ticket) sums the 16 per-batch
//          values, writes the mean, and resets all tickets for graph replay.
// Atomics only ELECT blocks; every float reduction is fixed-order -> deterministic.

#define HW      262144          // 512*512
#define HW4     65536           // HW / 4 (float4 units)
#define CH      4
#define BATCH   16
#define BPB     64              // blocks per batch
#define TPB     256             // threads per block

__device__ float2       g_partials[BATCH * BPB];
__device__ float        g_per_b[BATCH];
__device__ unsigned int g_batch_ticket[BATCH];
__device__ unsigned int g_done = 0;

__global__ __launch_bounds__(TPB) void masked_mse_fused(
    const float* __restrict__ input,
    const float* __restrict__ target,
    float* __restrict__ out)
{
    const int b   = blockIdx.y;
    const int tid = threadIdx.x;

    const float4* __restrict__ inb = (const float4*)(input  + (size_t)b * CH * HW);
    const float4* __restrict__ tgb = (const float4*)(target + (size_t)b * (CH + 1) * HW);
    const float4* __restrict__ mb  = (const float4*)(target + (size_t)b * (CH + 1) * HW + (size_t)CH * HW);

    float sse = 0.0f;
    float cnt = 0.0f;

    // 65536 vec4 per batch / (64 blocks * 256 threads) = 4 iterations/thread
    for (int p = blockIdx.x * TPB + tid; p < HW4; p += BPB * TPB) {
        const float4 m = mb[p];
        cnt += m.x + m.y + m.z + m.w;
        #pragma unroll
        for (int c = 0; c < CH; c++) {
            const float4 a = inb[c * HW4 + p];
            const float4 t = tgb[c * HW4 + p];
            const float dx = a.x - t.x;
            const float dy = a.y - t.y;
            const float dz = a.z - t.z;
            const float dw = a.w - t.w;
            sse += m.x * (dx * dx);
            sse += m.y * (dy * dy);
            sse += m.z * (dz * dz);
            sse += m.w * (dw * dw);
        }
    }

    // intra-warp reduce
    #pragma unroll
    for (int o = 16; o > 0; o >>= 1) {
        sse += __shfl_down_sync(0xFFFFFFFFu, sse, o);
        cnt += __shfl_down_sync(0xFFFFFFFFu, cnt, o);
    }

    __shared__ float s_sse[TPB / 32];
    __shared__ float s_cnt[TPB / 32];
    const int lane = tid & 31;
    const int wid  = tid >> 5;
    if (lane == 0) { s_sse[wid] = sse; s_cnt[wid] = cnt; }
    __syncthreads();

    // Only warp 0 continues; other warps are done.
    if (wid != 0) return;

    sse = (lane < TPB / 32) ? s_sse[lane] : 0.0f;
    cnt = (lane < TPB / 32) ? s_cnt[lane] : 0.0f;
    #pragma unroll
    for (int o = 4; o > 0; o >>= 1) {
        sse += __shfl_down_sync(0xFFFFFFFFu, sse, o);
        cnt += __shfl_down_sync(0xFFFFFFFFu, cnt, o);
    }

    unsigned int t = 0;
    if (lane == 0) {
        g_partials[b * BPB + blockIdx.x] = make_float2(sse, cnt);
        __threadfence();                       // release partial
        t = atomicAdd(&g_batch_ticket[b], 1u); // elect per-batch folder
    }
    t = __shfl_sync(0xFFFFFFFFu, t, 0);
    if (t != BPB - 1) return;

    // ---- Level 1: fold this batch's 64 partials (fixed order) ----
    __threadfence();                           // acquire all partials of batch b
    const float2 p0 = g_partials[b * BPB + lane];
    const float2 p1 = g_partials[b * BPB + lane + 32];
    float bs = p0.x + p1.x;
    float bc = p0.y + p1.y;
    #pragma unroll
    for (int o = 16; o > 0; o >>= 1) {
        bs += __shfl_down_sync(0xFFFFFFFFu, bs, o);
        bc += __shfl_down_sync(0xFFFFFFFFu, bc, o);
    }

    unsigned int d = 0;
    if (lane == 0) {
        g_per_b[b] = (bc > 0.0f) ? bs / ((float)CH * bc) : 0.0f;
        __threadfence();                       // release per-batch value
        d = atomicAdd(&g_done, 1u);            // elect global finisher
    }
    d = __shfl_sync(0xFFFFFFFFu, d, 0);
    if (d != BATCH - 1) return;

    // ---- Level 2: final mean over batches (fixed order, one thread) ----
    __threadfence();                           // acquire all per-batch values
    if (lane == 0) {
        float total = 0.0f;
        #pragma unroll
        for (int i = 0; i < BATCH; i++) total += g_per_b[i];
        out[0] = total / (float)BATCH;
        // reset tickets for the next graph replay
        #pragma unroll
        for (int i = 0; i < BATCH; i++) g_batch_ticket[i] = 0;
        g_done = 0;
    }
}

extern "C" void kernel_launch(void* const* d_in, const int* in_sizes, int n_in,
                              void* d_out, int out_size)
{
    const float* input  = (const float*)d_in[0];
    const float* target = (const float*)d_in[1];
    float*       out    = (float*)d_out;

    dim3 grid(BPB, BATCH);
    masked_mse_fused<<<grid, TPB>>>(input, target, out);
}

// round 11
// speedup vs baseline: 1.0011x; 1.0011x over previous
#include <cuda_runtime.h>

// MaskedMSE: B=16, C=4, H=W=512 — single kernel; 1024 streaming blocks +
// one dedicated spinner/folder block. Release/acquire atomics only (no
// __threadfence / CCTL.IVALL on the streaming path).
//
// input : d_in[0]  float32 [16, 4, 512, 512]
// target: d_in[1]  float32 [16, 5, 512, 512]  (channel 4 is the {0,1} mask)
// out   : d_out    float32 [1]
//
// Streaming block i (i < 1024): batch b = i>>6, sub-block blk = i&63.
//   Computes (masked SSE, mask count) partial, stores it, then
//   red.release.gpu.add g_ticket, 1   (release orders the partial store).
// Folder block (i == 1024): spins on ld.acquire.gpu g_ticket until 1024,
//   folds all partials in FIXED order (deterministic — atomics only count),
//   per_b = cnt>0 ? sse/(C*cnt) : 0, writes mean over B, resets the ticket
//   for the next graph replay. Zero-init of the ticket is correct on call 1.

#define HW      262144          // 512*512
#define HW4     65536           // HW / 4 (float4 units)
#define CH      4
#define BATCH   16
#define BPB     64              // streaming blocks per batch
#define TPB     256             // threads per block
#define NSTREAM (BATCH * BPB)   // 1024 streaming blocks

__device__ float2       g_partials[NSTREAM];
__device__ unsigned int g_ticket = 0;

__global__ __launch_bounds__(TPB) void masked_mse_spin(
    const float* __restrict__ input,
    const float* __restrict__ target,
    float* __restrict__ out)
{
    const int tid  = threadIdx.x;
    const int lane = tid & 31;
    const int wid  = tid >> 5;

    // ---------------- folder block ----------------
    if (blockIdx.x == NSTREAM) {
        if (tid == 0) {
            unsigned int v;
            for (;;) {
                asm volatile("ld.acquire.gpu.global.u32 %0, [%1];"
                             : "=r"(v) : "l"(&g_ticket) : "memory");
                if (v >= NSTREAM) break;
                __nanosleep(64);
            }
        }
        __syncthreads();   // releases once thread 0 has observed completion

        // 8 warps; warp w folds batches 2w and 2w+1 (fixed order).
        __shared__ float s_per_b[BATCH];
        #pragma unroll
        for (int i = 0; i < 2; i++) {
            const int b = wid * 2 + i;
            const float2 p0 = __ldcg(&g_partials[b * BPB + lane]);
            const float2 p1 = __ldcg(&g_partials[b * BPB + lane + 32]);
            float bs = p0.x + p1.x;
            float bc = p0.y + p1.y;
            #pragma unroll
            for (int o = 16; o > 0; o >>= 1) {
                bs += __shfl_down_sync(0xFFFFFFFFu, bs, o);
                bc += __shfl_down_sync(0xFFFFFFFFu, bc, o);
            }
            if (lane == 0)
                s_per_b[b] = (bc > 0.0f) ? bs / ((float)CH * bc) : 0.0f;
        }
        __syncthreads();

        if (tid == 0) {
            float total = 0.0f;
            #pragma unroll
            for (int i = 0; i < BATCH; i++) total += s_per_b[i];
            out[0] = total / (float)BATCH;
            g_ticket = 0;   // reset for the next graph replay
        }
        return;
    }

    // ---------------- streaming blocks ----------------
    const int b   = blockIdx.x >> 6;   // batch
    const int blk = blockIdx.x & 63;   // sub-block within batch

    const float4* __restrict__ inb = (const float4*)(input  + (size_t)b * CH * HW);
    const float4* __restrict__ tgb = (const float4*)(target + (size_t)b * (CH + 1) * HW);
    const float4* __restrict__ mb  = (const float4*)(target + (size_t)b * (CH + 1) * HW + (size_t)CH * HW);

    float sse = 0.0f;
    float cnt = 0.0f;

    // 65536 vec4 per batch / (64 blocks * 256 threads) = 4 iterations/thread
    for (int p = blk * TPB + tid; p < HW4; p += BPB * TPB) {
        const float4 m = mb[p];
        cnt += m.x + m.y + m.z + m.w;
        #pragma unroll
        for (int c = 0; c < CH; c++) {
            const float4 a = inb[c * HW4 + p];
            const float4 t = tgb[c * HW4 + p];
            const float dx = a.x - t.x;
            const float dy = a.y - t.y;
            const float dz = a.z - t.z;
            const float dw = a.w - t.w;
            sse += m.x * (dx * dx);
            sse += m.y * (dy * dy);
            sse += m.z * (dz * dz);
            sse += m.w * (dw * dw);
        }
    }

    // intra-warp reduce
    #pragma unroll
    for (int o = 16; o > 0; o >>= 1) {
        sse += __shfl_down_sync(0xFFFFFFFFu, sse, o);
        cnt += __shfl_down_sync(0xFFFFFFFFu, cnt, o);
    }

    __shared__ float s_sse[TPB / 32];
    __shared__ float s_cnt[TPB / 32];
    if (lane == 0) { s_sse[wid] = sse; s_cnt[wid] = cnt; }
    __syncthreads();

    if (wid != 0) return;

    sse = (lane < TPB / 32) ? s_sse[lane] : 0.0f;
    cnt = (lane < TPB / 32) ? s_cnt[lane] : 0.0f;
    #pragma unroll
    for (int o = 4; o > 0; o >>= 1) {
        sse += __shfl_down_sync(0xFFFFFFFFu, sse, o);
        cnt += __shfl_down_sync(0xFFFFFFFFu, cnt, o);
    }

    if (lane == 0) {
        g_partials[b * BPB + blk] = make_float2(sse, cnt);
        // Release: orders the partial store before the count increment.
        // RED (no return) — no round-trip, no L1 flush.
        asm volatile("red.release.gpu.global.add.u32 [%0], 1;"
                     :: "l"(&g_ticket) : "memory");
    }
}

extern "C" void kernel_launch(void* const* d_in, const int* in_sizes, int n_in,
                              void* d_out, int out_size)
{
    const float* input  = (const float*)d_in[0];
    const float* target = (const float*)d_in[1];
    float*       out    = (float*)d_out;

    masked_mse_spin<<<NSTREAM + 1, TPB>>>(input, target, out);
}